// round 12
// baseline (speedup 1.0000x reference)
#include <cuda_runtime.h>
#include <cuda_bf16.h>
#include <cstdint>

// HighOrderActivation: simplex interpolation over K=4 corners of a 2^4 table.
// X: [B=1024, D=512, 4] f32, params: [D=512, 16, 64] f32, out: [B, D, 64] f32.
//
// out[b,d,:] = c0*T[15] + c1*T[ind1] + c2*T[ind2] + c3*T[ind3]
//   where xs = sort(X[b,d,:]), c = [xs0, diffs], ind from reverse bit-cumsum.
//
// Branchless uint-key sort: key = order_preserving_uint(f) with the 2-bit
// source index packed into the low mantissa bits; 5-comparator umin/umax
// network (IMNMX, lat 4, ~20 cyc depth — replaces ~70-90 cyc of predicated
// compare-swap chain). Index = key & 3; value decoded by inverting the
// transform. Low-bit clobber costs ~2e-7 rel err (gate 1e-3). Tie order =
// ascending source index = stable argsort semantics.
//
// Blocking: grid = (B/BCHUNK, D), one d per block; params[d] (4 KB) and the
// block's X (2 KB) staged in smem; row 15 cached in registers; 8 threads per
// pair, two float4 output slots per thread (perfect 128 B STG segments).

#define B_DIM  1024
#define D_DIM  512
#define TBL_ROWS 16
#define BCHUNK 128
#define THREADS_PER_BLOCK 256
#define PAIRS_PER_ITER (THREADS_PER_BLOCK / 8)   // 32
#define ITERS (BCHUNK / PAIRS_PER_ITER)          // 4

// Order-preserving float->uint key with 2-bit index packed in the LSBs.
static __device__ __forceinline__ uint32_t fkey(float f, uint32_t i) {
    uint32_t u = __float_as_uint(f);
    uint32_t m = (uint32_t)((int32_t)u >> 31);          // ~0 if negative
    uint32_t k = u ^ (m | 0x80000000u);
    return (k & ~3u) | i;
}

// Inverse transform (idx bits cleared first).
static __device__ __forceinline__ float fdec(uint32_t k) {
    uint32_t kc = k & ~3u;
    uint32_t m  = (uint32_t)((int32_t)kc >> 31);        // ~0 if originally >= 0
    return __uint_as_float(kc ^ (~m | 0x80000000u));
}

__global__ __launch_bounds__(THREADS_PER_BLOCK, 6)
void hoa_kernel(const float* __restrict__ X,
                const float* __restrict__ params,
                float* __restrict__ out)
{
    __shared__ float4 tab[TBL_ROWS * 16];  // params[d]: 16 rows x 16 float4 = 4 KB
    __shared__ float4 xs[BCHUNK];          // X for this block's pairs = 2 KB

    const int tid = threadIdx.x;
    const int d   = blockIdx.y;
    const int b0  = blockIdx.x * BCHUNK;

    tab[tid] = reinterpret_cast<const float4*>(params)[(size_t)d * (TBL_ROWS * 16) + tid];
    if (tid < BCHUNK) {
        xs[tid] = reinterpret_cast<const float4*>(X)[(size_t)(b0 + tid) * D_DIM + d];
    }
    __syncthreads();

    const int o         = tid & 7;    // float4 slots o and o+8
    const int pair_base = tid >> 3;   // 0..31

    // Row 15 (used by every output) cached in registers.
    const float4 r15a = tab[15 * 16 + o];
    const float4 r15b = tab[15 * 16 + o + 8];

    #pragma unroll
    for (int it = 0; it < ITERS; ++it) {
        const int pr = it * PAIRS_PER_ITER + pair_base;
        const size_t p = (size_t)(b0 + pr) * D_DIM + d;

        // Broadcast LDS: 8 threads of a pair read the same 16 B.
        const float4 xv = xs[pr];

        // Build sortable keys (all four independent -> full ILP).
        uint32_t k0 = fkey(xv.x, 0);
        uint32_t k1 = fkey(xv.y, 1);
        uint32_t k2 = fkey(xv.z, 2);
        uint32_t k3 = fkey(xv.w, 3);

        // 5-comparator network, branchless (IMNMX pairs).
#define USWAP(a, b_)                                   \
        do {                                           \
            uint32_t lo = min(a, b_);                  \
            uint32_t hi = max(a, b_);                  \
            a = lo; b_ = hi;                           \
        } while (0)
        USWAP(k0, k1);
        USWAP(k2, k3);
        USWAP(k0, k2);
        USWAP(k1, k3);
        USWAP(k1, k2);
#undef USWAP

        // Decode sorted values and original indices.
        const float v0 = fdec(k0);
        const float v1 = fdec(k1);
        const float v2 = fdec(k2);
        const float v3 = fdec(k3);
        const int   i0 = (int)(k0 & 3u);
        const int   i1 = (int)(k1 & 3u);
        const int   i3 = (int)(k3 & 3u);

        // Corner indices (ind0 == 15 always).
        const int ind1 = 15 - (1 << i0);
        const int ind2 = ind1 - (1 << i1);
        const int ind3 = (1 << i3);

        // Simplex coefficients.
        const float c0 = v0;
        const float c1 = v1 - v0;
        const float c2 = v2 - v1;
        const float c3 = v3 - v2;

        // Gather 3 rows x 2 slots from smem (LDS.128, conflict-free).
        const float4 g1a = tab[ind1 * 16 + o];
        const float4 g1b = tab[ind1 * 16 + o + 8];
        const float4 g2a = tab[ind2 * 16 + o];
        const float4 g2b = tab[ind2 * 16 + o + 8];
        const float4 g3a = tab[ind3 * 16 + o];
        const float4 g3b = tab[ind3 * 16 + o + 8];

        float4 ra, rb;
        ra.x = c0 * r15a.x + c1 * g1a.x + c2 * g2a.x + c3 * g3a.x;
        ra.y = c0 * r15a.y + c1 * g1a.y + c2 * g2a.y + c3 * g3a.y;
        ra.z = c0 * r15a.z + c1 * g1a.z + c2 * g2a.z + c3 * g3a.z;
        ra.w = c0 * r15a.w + c1 * g1a.w + c2 * g2a.w + c3 * g3a.w;

        rb.x = c0 * r15b.x + c1 * g1b.x + c2 * g2b.x + c3 * g3b.x;
        rb.y = c0 * r15b.y + c1 * g1b.y + c2 * g2b.y + c3 * g3b.y;
        rb.z = c0 * r15b.z + c1 * g1b.z + c2 * g2b.z + c3 * g3b.z;
        rb.w = c0 * r15b.w + c1 * g1b.w + c2 * g2b.w + c3 * g3b.w;

        // Two STG.E.128; the pair covers its 256 B row as two coalesced
        // 128 B segments.
        float4* orow = reinterpret_cast<float4*>(out) + p * 16;
        orow[o]     = ra;
        orow[o + 8] = rb;
    }
}

extern "C" void kernel_launch(void* const* d_in, const int* in_sizes, int n_in,
                              void* d_out, int out_size)
{
    const float* X      = (const float*)d_in[0];   // [B, D, 4] f32
    const float* params = (const float*)d_in[1];   // [D, 16, 64] f32
    float*       out    = (float*)d_out;           // [B, D, 64] f32

    dim3 grid(B_DIM / BCHUNK, D_DIM);              // (8, 512) = 4096 blocks
    hoa_kernel<<<grid, THREADS_PER_BLOCK>>>(X, params, out);
}